// round 4
// baseline (speedup 1.0000x reference)
#include <cuda_runtime.h>
#include <cstdint>

// Unfold (im2col): x[16,96,56,56] f32, 3x3 window, pad 1
// out[(bc*9 + k)*3136 + h*56 + w] = x_pad[bc][h+ki][w+kj],  k = ki*3+kj
//
// v4: stage output tile in SMEM (STS.128), ship with TMA 1D bulk stores
// (cp.async.bulk.global.shared::cta) -- removes all STG wavefronts from the
// L1/LSU path. One block = one (bc, 28-row half-image).

#define B_ 16
#define C_ 96
#define H_ 56
#define W_ 56
#define HW_ (H_ * W_)            // 3136
#define TROWS_ 28                // tile rows per block
#define W4_ (W_ / 4)             // 14 float4 per row
#define ITEMS_ (TROWS_ * W4_)    // 392 work items per block
#define TILE_FLOATS_ (9 * TROWS_ * W_)        // 14112
#define TILE_BYTES_ (TILE_FLOATS_ * 4)        // 56448
#define SLICE_BYTES_ (TROWS_ * W_ * 4)        // 6272 per k

__device__ __forceinline__ uint32_t smem_u32(const void* p) {
    uint32_t a;
    asm("{ .reg .u64 t; cvta.to.shared.u64 t, %1; cvt.u32.u64 %0, t; }"
        : "=r"(a) : "l"(p));
    return a;
}

extern __shared__ float out_s[];   // [9][28][56]

__global__ __launch_bounds__(256) void unfold_kernel(
    const float* __restrict__ x, float* __restrict__ out)
{
    int bc = blockIdx.x >> 1;
    int h0 = (blockIdx.x & 1) * TROWS_;
    int lane = threadIdx.x & 31;

    const float* base = x + (size_t)bc * HW_;

    #pragma unroll
    for (int it = 0; it < 2; it++) {
        int idx = threadIdx.x + it * 256;
        bool active = idx < ITEMS_;
        int h  = idx / W4_;          // local row 0..27
        int w4 = idx - h * W4_;      // 0..13
        int w  = w4 * 4;
        int gh = h0 + h;

        #pragma unroll
        for (int r = 0; r < 3; r++) {
            int  sh = gh + r - 1;
            bool ok = active & (sh >= 0) & (sh < H_);
            const float* rp = base + sh * W_ + w;

            float4 m = make_float4(0.f, 0.f, 0.f, 0.f);
            if (ok) m = *reinterpret_cast<const float4*>(rp);

            float left  = __shfl_up_sync(0xffffffffu, m.w, 1);
            float right = __shfl_down_sync(0xffffffffu, m.x, 1);

            // warp-boundary fallbacks (row wraps inside the image never need
            // them: w4==0 / w4==13 are the padded image edges)
            if (lane == 0  && ok && w4 > 0)        left  = __ldg(rp - 1);
            if (lane == 31 && ok && w4 < W4_ - 1)  right = __ldg(rp + 4);
            if (w4 == 0)        left  = 0.f;
            if (w4 == W4_ - 1)  right = 0.f;

            if (active) {
                float* o = out_s + ((r * 3) * TROWS_ + h) * W_ + w;
                *reinterpret_cast<float4*>(o)               = make_float4(left, m.x, m.y, m.z);
                *reinterpret_cast<float4*>(o + TROWS_ * W_) = m;
                *reinterpret_cast<float4*>(o + 2 * TROWS_ * W_) = make_float4(m.y, m.z, m.w, right);
            }
        }
    }

    // make STS visible to the async proxy, then one thread issues bulk stores
    asm volatile("fence.proxy.async.shared::cta;" ::: "memory");
    __syncthreads();

    if (threadIdx.x == 0) {
        uint32_t s = smem_u32(out_s);
        float* g = out + ((size_t)bc * 9) * HW_ + h0 * W_;
        #pragma unroll
        for (int k = 0; k < 9; k++) {
            asm volatile(
                "cp.async.bulk.global.shared::cta.bulk_group [%0], [%1], %2;"
                :: "l"(g + (size_t)k * HW_), "r"(s + k * SLICE_BYTES_),
                   "n"(SLICE_BYTES_)
                : "memory");
        }
        asm volatile("cp.async.bulk.commit_group;" ::: "memory");
        asm volatile("cp.async.bulk.wait_group 0;" ::: "memory");  // smem reuse hazard
    }
}

extern "C" void kernel_launch(void* const* d_in, const int* in_sizes, int n_in,
                              void* d_out, int out_size)
{
    const float* x = (const float*)d_in[0];
    float* out = (float*)d_out;
    static bool attr_set = false;
    if (!attr_set) {
        cudaFuncSetAttribute(unfold_kernel,
                             cudaFuncAttributeMaxDynamicSharedMemorySize,
                             TILE_BYTES_);
        attr_set = true;
    }
    unfold_kernel<<<B_ * C_ * 2, 256, TILE_BYTES_>>>(x, out);
}

// round 5
// speedup vs baseline: 1.1215x; 1.1215x over previous
#include <cuda_runtime.h>

// Unfold (im2col): x[16,96,56,56] f32, 3x3 window, pad 1
// out[(bc*9 + ki*3+kj)*3136 + h*56+w] = x_pad[bc][h+ki][w+kj]
//
// v5: one thread = (bc, 4-row group, w4). Loads 6 input rows once
// (vs 3x redundancy in v3), emits 36 streaming STG.128 for the 4 output
// rows x 9 window positions. Halos via warp shuffle + rare lane fallbacks.

#define B_ 16
#define C_ 96
#define H_ 56
#define W_ 56
#define HW_ (H_ * W_)            // 3136
#define W4_ (W_ / 4)             // 14
#define HG_ (H_ / 4)             // 14 row-groups
#define ITEMS_ (HG_ * W4_)       // 196 per bc
#define NTHREADS_ (B_ * C_ * ITEMS_)   // 301,056 = 1176 * 256 exactly

__global__ __launch_bounds__(256) void unfold_kernel(
    const float* __restrict__ x, float* __restrict__ out)
{
    int tid  = blockIdx.x * 256 + threadIdx.x;   // grid exact, no guard
    int lane = threadIdx.x & 31;

    int rest = tid % ITEMS_;
    int bc   = tid / ITEMS_;
    int hg   = rest / W4_;
    int w4   = rest - hg * W4_;
    int h0   = hg * 4;
    int w    = w4 * 4;

    const float* base = x + (size_t)bc * HW_;

    // Stage 6 input rows (h0-1 .. h0+4), each as [left, f4, right]
    float a[6][6];
    #pragma unroll
    for (int r = 0; r < 6; r++) {
        int  sh = h0 + r - 1;
        bool ok = (sh >= 0) & (sh < H_);
        const float* rp = base + sh * W_ + w;

        float4 m = make_float4(0.f, 0.f, 0.f, 0.f);
        if (ok) m = *reinterpret_cast<const float4*>(rp);   // predicated LDG.128

        float left  = __shfl_up_sync(0xffffffffu, m.w, 1);
        float right = __shfl_down_sync(0xffffffffu, m.x, 1);

        if (lane == 0  && ok && w4 > 0)        left  = __ldg(rp - 1);
        if (lane == 31 && ok && w4 < W4_ - 1)  right = __ldg(rp + 4);
        if (w4 == 0)        left  = 0.f;
        if (w4 == W4_ - 1)  right = 0.f;

        a[r][0] = left;
        a[r][1] = m.x; a[r][2] = m.y; a[r][3] = m.z; a[r][4] = m.w;
        a[r][5] = right;
    }

    // 4 output rows x 9 window positions = 36 streaming STG.128
    float* ob = out + (size_t)bc * 9 * HW_ + h0 * W_ + w;
    #pragma unroll
    for (int oh = 0; oh < 4; oh++) {
        float* o = ob + oh * W_;
        #pragma unroll
        for (int ki = 0; ki < 3; ki++) {
            const float* row = a[oh + ki];
            #pragma unroll
            for (int kj = 0; kj < 3; kj++) {
                float4 v = make_float4(row[kj], row[kj + 1],
                                       row[kj + 2], row[kj + 3]);
                __stcs(reinterpret_cast<float4*>(o + (size_t)(ki * 3 + kj) * HW_), v);
            }
        }
    }
}

extern "C" void kernel_launch(void* const* d_in, const int* in_sizes, int n_in,
                              void* d_out, int out_size)
{
    const float* x = (const float*)d_in[0];
    float* out = (float*)d_out;
    unfold_kernel<<<NTHREADS_ / 256, 256>>>(x, out);
}